// round 1
// baseline (speedup 1.0000x reference)
#include <cuda_runtime.h>

// Non-local block = attention with head_dim=32, N=6400, B=2, fp32.
// Stage 1: channel projections -> Q (theta), K (phi), V (g) in [B, N, 32] scratch.
// Stage 2: flash-attention style online softmax, split-K (5 splits) for occupancy.
// Stage 3: merge partials + output projection (w_w) + residual add.

#define BATCH 2
#define CH 64
#define DI 32
#define NP 6400
#define TQ 128
#define TK 64
#define SPLITS 5
#define KEYS_PER_SPLIT (NP / SPLITS)   // 1280, exact

__device__ float g_Q[BATCH * NP * DI];
__device__ float g_K[BATCH * NP * DI];
__device__ float g_V[BATCH * NP * DI];
__device__ float g_acc[BATCH * SPLITS * NP * DI];
__device__ float g_mp[BATCH * SPLITS * NP];
__device__ float g_lp[BATCH * SPLITS * NP];

// ---------------------------------------------------------------------------
// Stage 1: Q/K/V projection. Block = 128 positions, 128 threads.
// ---------------------------------------------------------------------------
__global__ void __launch_bounds__(TQ) proj_kernel(
    const float* __restrict__ x,
    const float* __restrict__ theta_w,
    const float* __restrict__ phi_w,
    const float* __restrict__ gw)
{
    __shared__ float ws[3 * DI * CH];  // [theta | phi | g], each [i*64+c]
    __shared__ float xs[CH * TQ];

    const int b   = blockIdx.y;
    const int n0  = blockIdx.x * TQ;
    const int tid = threadIdx.x;

    for (int i = tid; i < DI * CH; i += TQ) {
        ws[i]               = theta_w[i];
        ws[DI * CH + i]     = phi_w[i];
        ws[2 * DI * CH + i] = gw[i];
    }
    const float* xb = x + b * CH * NP + n0;
    #pragma unroll
    for (int c = 0; c < CH; c++)
        xs[c * TQ + tid] = xb[c * NP + tid];
    __syncthreads();

    float xr[CH];
    #pragma unroll
    for (int c = 0; c < CH; c++) xr[c] = xs[c * TQ + tid];

    const int n = n0 + tid;
    float* Qp = g_Q + (b * NP + n) * DI;
    float* Kp = g_K + (b * NP + n) * DI;
    float* Vp = g_V + (b * NP + n) * DI;

    #pragma unroll 1
    for (int i0 = 0; i0 < DI; i0 += 4) {
        float t[4] = {0.f, 0.f, 0.f, 0.f};
        float p[4] = {0.f, 0.f, 0.f, 0.f};
        float g[4] = {0.f, 0.f, 0.f, 0.f};
        #pragma unroll
        for (int c = 0; c < CH; c++) {
            float xv = xr[c];
            #pragma unroll
            for (int k = 0; k < 4; k++) {
                t[k] = fmaf(ws[(i0 + k) * CH + c], xv, t[k]);
                p[k] = fmaf(ws[DI * CH + (i0 + k) * CH + c], xv, p[k]);
                g[k] = fmaf(ws[2 * DI * CH + (i0 + k) * CH + c], xv, g[k]);
            }
        }
        *(float4*)(Qp + i0) = make_float4(t[0], t[1], t[2], t[3]);
        *(float4*)(Kp + i0) = make_float4(p[0], p[1], p[2], p[3]);
        *(float4*)(Vp + i0) = make_float4(g[0], g[1], g[2], g[3]);
    }
}

// ---------------------------------------------------------------------------
// Stage 2: split-K flash attention. Block = 128 queries, thread = 1 query.
// grid: (N/TQ, SPLITS, BATCH)
// ---------------------------------------------------------------------------
__global__ void __launch_bounds__(TQ) attn_kernel()
{
    __shared__ float ks[TK * DI];
    __shared__ float vs[TK * DI];

    const int b     = blockIdx.z;
    const int split = blockIdx.y;
    const int tid   = threadIdx.x;
    const int n     = blockIdx.x * TQ + tid;

    // load q into registers
    float q[DI];
    {
        const float4* Qp = (const float4*)(g_Q + (b * NP + n) * DI);
        #pragma unroll
        for (int d4 = 0; d4 < 8; d4++) {
            float4 t = Qp[d4];
            q[4 * d4 + 0] = t.x; q[4 * d4 + 1] = t.y;
            q[4 * d4 + 2] = t.z; q[4 * d4 + 3] = t.w;
        }
    }

    float acc[DI];
    #pragma unroll
    for (int d = 0; d < DI; d++) acc[d] = 0.f;
    float m = -1e30f, l = 0.f;

    const int k0base = split * KEYS_PER_SPLIT;
    const float4* Kb = (const float4*)(g_K + b * NP * DI);
    const float4* Vb = (const float4*)(g_V + b * NP * DI);

    for (int kt = 0; kt < KEYS_PER_SPLIT; kt += TK) {
        const int krow0 = k0base + kt;
        // cooperative tile load: TK*DI/4 = 512 float4 / 128 threads = 4 each
        #pragma unroll
        for (int r = 0; r < 4; r++) {
            int idx = r * TQ + tid;
            ((float4*)ks)[idx] = Kb[krow0 * (DI / 4) + idx];
            ((float4*)vs)[idx] = Vb[krow0 * (DI / 4) + idx];
        }
        __syncthreads();

        #pragma unroll 1
        for (int j0 = 0; j0 < TK; j0 += 16) {
            float s[16];
            #pragma unroll
            for (int jj = 0; jj < 16; jj++) {
                const float4* kr = (const float4*)(ks + (j0 + jj) * DI);
                float sv = 0.f;
                #pragma unroll
                for (int d4 = 0; d4 < 8; d4++) {
                    float4 kk = kr[d4];
                    sv = fmaf(q[4 * d4 + 0], kk.x, sv);
                    sv = fmaf(q[4 * d4 + 1], kk.y, sv);
                    sv = fmaf(q[4 * d4 + 2], kk.z, sv);
                    sv = fmaf(q[4 * d4 + 3], kk.w, sv);
                }
                s[jj] = sv;
            }
            float cm = s[0];
            #pragma unroll
            for (int jj = 1; jj < 16; jj++) cm = fmaxf(cm, s[jj]);
            if (cm > m) {
                float scale = __expf(m - cm);
                m = cm;
                l *= scale;
                #pragma unroll
                for (int d = 0; d < DI; d++) acc[d] *= scale;
            }
            #pragma unroll
            for (int jj = 0; jj < 16; jj++) {
                float p = __expf(s[jj] - m);
                l += p;
                const float4* vr = (const float4*)(vs + (j0 + jj) * DI);
                #pragma unroll
                for (int d4 = 0; d4 < 8; d4++) {
                    float4 vv = vr[d4];
                    acc[4 * d4 + 0] = fmaf(p, vv.x, acc[4 * d4 + 0]);
                    acc[4 * d4 + 1] = fmaf(p, vv.y, acc[4 * d4 + 1]);
                    acc[4 * d4 + 2] = fmaf(p, vv.z, acc[4 * d4 + 2]);
                    acc[4 * d4 + 3] = fmaf(p, vv.w, acc[4 * d4 + 3]);
                }
            }
        }
        __syncthreads();
    }

    const int pidx = (b * SPLITS + split) * NP + n;
    float* ap = g_acc + (long long)pidx * DI;
    #pragma unroll
    for (int d = 0; d < DI; d += 4)
        *(float4*)(ap + d) = make_float4(acc[d], acc[d + 1], acc[d + 2], acc[d + 3]);
    g_mp[pidx] = m;
    g_lp[pidx] = l;
}

// ---------------------------------------------------------------------------
// Stage 3: merge split partials, output projection, residual add.
// grid: (N/TQ, BATCH)
// ---------------------------------------------------------------------------
__global__ void __launch_bounds__(TQ) merge_out_kernel(
    const float* __restrict__ x,
    const float* __restrict__ w_w,
    float* __restrict__ out)
{
    __shared__ float ws[CH * DI];
    const int b   = blockIdx.y;
    const int tid = threadIdx.x;
    const int n   = blockIdx.x * TQ + tid;

    for (int i = tid; i < CH * DI; i += TQ) ws[i] = w_w[i];
    __syncthreads();

    float mv[SPLITS], lv[SPLITS];
    float M = -1e30f;
    #pragma unroll
    for (int s = 0; s < SPLITS; s++) {
        int pidx = (b * SPLITS + s) * NP + n;
        mv[s] = g_mp[pidx];
        lv[s] = g_lp[pidx];
        M = fmaxf(M, mv[s]);
    }

    float L = 0.f;
    float y[DI];
    #pragma unroll
    for (int d = 0; d < DI; d++) y[d] = 0.f;

    #pragma unroll
    for (int s = 0; s < SPLITS; s++) {
        float w = __expf(mv[s] - M);
        L += lv[s] * w;
        const float4* ap = (const float4*)(g_acc + (long long)((b * SPLITS + s) * NP + n) * DI);
        #pragma unroll
        for (int d4 = 0; d4 < 8; d4++) {
            float4 a = ap[d4];
            y[4 * d4 + 0] = fmaf(w, a.x, y[4 * d4 + 0]);
            y[4 * d4 + 1] = fmaf(w, a.y, y[4 * d4 + 1]);
            y[4 * d4 + 2] = fmaf(w, a.z, y[4 * d4 + 2]);
            y[4 * d4 + 3] = fmaf(w, a.w, y[4 * d4 + 3]);
        }
    }
    float inv = 1.f / L;
    #pragma unroll
    for (int d = 0; d < DI; d++) y[d] *= inv;

    const float* xb = x + b * CH * NP + n;
    float* ob = out + b * CH * NP + n;
    #pragma unroll 1
    for (int c = 0; c < CH; c++) {
        float o = xb[c * NP];
        #pragma unroll
        for (int i = 0; i < DI; i++)
            o = fmaf(ws[c * DI + i], y[i], o);
        ob[c * NP] = o;
    }
}

// ---------------------------------------------------------------------------
extern "C" void kernel_launch(void* const* d_in, const int* in_sizes, int n_in,
                              void* d_out, int out_size)
{
    const float* x       = (const float*)d_in[0];
    const float* gw      = (const float*)d_in[1];
    const float* theta_w = (const float*)d_in[2];
    const float* phi_w   = (const float*)d_in[3];
    const float* w_w     = (const float*)d_in[4];
    float* out           = (float*)d_out;

    dim3 gp(NP / TQ, BATCH);
    proj_kernel<<<gp, TQ>>>(x, theta_w, phi_w, gw);

    dim3 ga(NP / TQ, SPLITS, BATCH);
    attn_kernel<<<ga, TQ>>>();

    merge_out_kernel<<<gp, TQ>>>(x, w_w, out);
}

// round 2
// speedup vs baseline: 1.1612x; 1.1612x over previous
#include <cuda_runtime.h>

// Non-local block = attention, head_dim=32, N=6400, B=2, fp32.
// R1: packed fma.rn.f32x2 (sm_103a dual-rate fp32) in all three stages.

#define BATCH 2
#define CH 64
#define DI 32
#define NP 6400
#define TQ 128
#define TK 64
#define SPLITS 5
#define KEYS_PER_SPLIT (NP / SPLITS)   // 1280

typedef unsigned long long u64;

__device__ __forceinline__ u64 f2fma(u64 a, u64 b, u64 c) {
    u64 d; asm("fma.rn.f32x2 %0,%1,%2,%3;" : "=l"(d) : "l"(a), "l"(b), "l"(c)); return d;
}
__device__ __forceinline__ u64 f2mul(u64 a, u64 b) {
    u64 d; asm("mul.rn.f32x2 %0,%1,%2;" : "=l"(d) : "l"(a), "l"(b)); return d;
}
__device__ __forceinline__ u64 f2pack(float x) {
    u64 d; asm("mov.b64 %0,{%1,%2};" : "=l"(d) : "f"(x), "f"(x)); return d;
}
__device__ __forceinline__ float f2hadd(u64 a) {
    float lo, hi; asm("mov.b64 {%0,%1},%2;" : "=f"(lo), "=f"(hi) : "l"(a)); return lo + hi;
}

__device__ float g_Q[BATCH * NP * DI];
__device__ float g_K[BATCH * NP * DI];
__device__ float g_V[BATCH * NP * DI];
__device__ float g_acc[BATCH * SPLITS * NP * DI];
__device__ float g_mp[BATCH * SPLITS * NP];
__device__ float g_lp[BATCH * SPLITS * NP];

// ---------------------------------------------------------------------------
// Stage 1: Q/K/V projection. 384 threads: warpgroup 0->theta, 1->phi, 2->g.
// ---------------------------------------------------------------------------
#define PT 384
__global__ void __launch_bounds__(PT) proj_kernel(
    const float* __restrict__ x,
    const float* __restrict__ theta_w,
    const float* __restrict__ phi_w,
    const float* __restrict__ gw)
{
    __shared__ __align__(16) float xs[CH * TQ];        // [c][p]
    __shared__ __align__(16) float wsT[3 * CH * DI];   // transposed [c][i]

    const int b   = blockIdx.y;
    const int n0  = blockIdx.x * TQ;
    const int tid = threadIdx.x;
    const int wg  = tid >> 7;       // 0..2
    const int wt  = tid & 127;      // position within tile

    const float* wsrc = (wg == 0) ? theta_w : (wg == 1) ? phi_w : gw;
    float*       dst  = (wg == 0) ? g_Q     : (wg == 1) ? g_K   : g_V;

    // transpose weights into smem: w[i][c] -> wsT[c][i]
    for (int idx = wt; idx < DI * CH; idx += 128) {
        int i = idx / CH, c = idx % CH;
        wsT[wg * CH * DI + c * DI + i] = wsrc[idx];
    }
    // x tile cooperative load
    const float* xb = x + b * CH * NP + n0;
    for (int idx = tid; idx < CH * TQ; idx += PT) {
        int c = idx >> 7, p = idx & 127;
        xs[idx] = xb[c * NP + p];
    }
    __syncthreads();

    u64 acc2[16];
    #pragma unroll
    for (int i = 0; i < 16; i++) acc2[i] = 0ull;

    const float* wp = wsT + wg * CH * DI;
    #pragma unroll 4
    for (int c = 0; c < CH; c++) {
        u64 x2 = f2pack(xs[c * TQ + wt]);
        const u64* w2 = (const u64*)(wp + c * DI);
        #pragma unroll
        for (int i2 = 0; i2 < 16; i2++)
            acc2[i2] = f2fma(w2[i2], x2, acc2[i2]);
    }

    ulonglong2* dp = (ulonglong2*)(dst + (b * NP + n0 + wt) * DI);
    #pragma unroll
    for (int i4 = 0; i4 < 8; i4++)
        dp[i4] = make_ulonglong2(acc2[2 * i4], acc2[2 * i4 + 1]);
}

// ---------------------------------------------------------------------------
// Stage 2: split-K flash attention, f32x2 math. Thread = 1 query.
// grid: (N/TQ, SPLITS, BATCH), single wave (500 blocks, 4 blocks/SM).
// ---------------------------------------------------------------------------
__global__ void __launch_bounds__(TQ, 4) attn_kernel()
{
    __shared__ __align__(16) float ks[TK * DI];
    __shared__ __align__(16) float vs[TK * DI];

    const int b     = blockIdx.z;
    const int split = blockIdx.y;
    const int tid   = threadIdx.x;
    const int n     = blockIdx.x * TQ + tid;

    u64 q2[16];
    {
        const ulonglong2* Qp = (const ulonglong2*)(g_Q + (b * NP + n) * DI);
        #pragma unroll
        for (int d8 = 0; d8 < 8; d8++) {
            ulonglong2 t = Qp[d8];
            q2[2 * d8] = t.x; q2[2 * d8 + 1] = t.y;
        }
    }

    u64 acc2[16];
    #pragma unroll
    for (int i = 0; i < 16; i++) acc2[i] = 0ull;
    float m = -1e30f, l = 0.f;

    const int k0base = split * KEYS_PER_SPLIT;
    const float4* Kb = (const float4*)(g_K + b * NP * DI);
    const float4* Vb = (const float4*)(g_V + b * NP * DI);

    for (int kt = 0; kt < KEYS_PER_SPLIT; kt += TK) {
        const int krow0 = k0base + kt;
        #pragma unroll
        for (int r = 0; r < 4; r++) {
            int idx = r * TQ + tid;
            ((float4*)ks)[idx] = Kb[krow0 * (DI / 4) + idx];
            ((float4*)vs)[idx] = Vb[krow0 * (DI / 4) + idx];
        }
        __syncthreads();

        #pragma unroll 1
        for (int j0 = 0; j0 < TK; j0 += 16) {
            float s[16];
            #pragma unroll
            for (int jj = 0; jj < 16; jj++) {
                const ulonglong2* kr = (const ulonglong2*)(ks + (j0 + jj) * DI);
                u64 s2 = 0ull;
                #pragma unroll
                for (int d8 = 0; d8 < 8; d8++) {
                    ulonglong2 kk = kr[d8];
                    s2 = f2fma(q2[2 * d8],     kk.x, s2);
                    s2 = f2fma(q2[2 * d8 + 1], kk.y, s2);
                }
                s[jj] = f2hadd(s2);
            }
            float cm = s[0];
            #pragma unroll
            for (int jj = 1; jj < 16; jj++) cm = fmaxf(cm, s[jj]);
            if (cm > m) {
                float scale = __expf(m - cm);
                m = cm;
                l *= scale;
                u64 sc2 = f2pack(scale);
                #pragma unroll
                for (int i = 0; i < 16; i++) acc2[i] = f2mul(acc2[i], sc2);
            }
            #pragma unroll
            for (int jj = 0; jj < 16; jj++) {
                float p = __expf(s[jj] - m);
                l += p;
                u64 p2 = f2pack(p);
                const ulonglong2* vr = (const ulonglong2*)(vs + (j0 + jj) * DI);
                #pragma unroll
                for (int d8 = 0; d8 < 8; d8++) {
                    ulonglong2 vv = vr[d8];
                    acc2[2 * d8]     = f2fma(p2, vv.x, acc2[2 * d8]);
                    acc2[2 * d8 + 1] = f2fma(p2, vv.y, acc2[2 * d8 + 1]);
                }
            }
        }
        __syncthreads();
    }

    const int pidx = (b * SPLITS + split) * NP + n;
    ulonglong2* ap = (ulonglong2*)(g_acc + (long long)pidx * DI);
    #pragma unroll
    for (int d8 = 0; d8 < 8; d8++)
        ap[d8] = make_ulonglong2(acc2[2 * d8], acc2[2 * d8 + 1]);
    g_mp[pidx] = m;
    g_lp[pidx] = l;
}

// ---------------------------------------------------------------------------
// Stage 3: merge partials + output projection + residual.
// 256 threads: half 0 -> channels 0..31, half 1 -> channels 32..63.
// ---------------------------------------------------------------------------
#define MT 256
__global__ void __launch_bounds__(MT) merge_out_kernel(
    const float* __restrict__ x,
    const float* __restrict__ w_w,
    float* __restrict__ out)
{
    __shared__ __align__(16) float ws[CH * DI];
    const int b    = blockIdx.y;
    const int tid  = threadIdx.x;
    const int half = tid >> 7;
    const int qt   = tid & 127;
    const int n    = blockIdx.x * TQ + qt;

    for (int i = tid; i < CH * DI; i += MT) ws[i] = w_w[i];
    __syncthreads();

    float mv[SPLITS], lv[SPLITS];
    float M = -1e30f;
    #pragma unroll
    for (int s = 0; s < SPLITS; s++) {
        int pidx = (b * SPLITS + s) * NP + n;
        mv[s] = g_mp[pidx];
        lv[s] = g_lp[pidx];
        M = fmaxf(M, mv[s]);
    }

    float L = 0.f;
    u64 y2[16];
    #pragma unroll
    for (int i = 0; i < 16; i++) y2[i] = 0ull;

    #pragma unroll
    for (int s = 0; s < SPLITS; s++) {
        float w = __expf(mv[s] - M);
        L += lv[s] * w;
        u64 w2 = f2pack(w);
        const ulonglong2* ap = (const ulonglong2*)(g_acc + (long long)((b * SPLITS + s) * NP + n) * DI);
        #pragma unroll
        for (int d8 = 0; d8 < 8; d8++) {
            ulonglong2 a = ap[d8];
            y2[2 * d8]     = f2fma(w2, a.x, y2[2 * d8]);
            y2[2 * d8 + 1] = f2fma(w2, a.y, y2[2 * d8 + 1]);
        }
    }
    u64 inv2 = f2pack(1.f / L);
    #pragma unroll
    for (int i = 0; i < 16; i++) y2[i] = f2mul(y2[i], inv2);

    const float* xb = x + b * CH * NP + n;
    float* ob = out + b * CH * NP + n;
    const int c0 = half * 32;
    #pragma unroll 2
    for (int c = c0; c < c0 + 32; c++) {
        const u64* w2p = (const u64*)(ws + c * DI);
        u64 o2 = 0ull;
        #pragma unroll
        for (int i2 = 0; i2 < 16; i2++)
            o2 = f2fma(w2p[i2], y2[i2], o2);
        ob[c * NP] = xb[c * NP] + f2hadd(o2);
    }
}

// ---------------------------------------------------------------------------
extern "C" void kernel_launch(void* const* d_in, const int* in_sizes, int n_in,
                              void* d_out, int out_size)
{
    const float* x       = (const float*)d_in[0];
    const float* gw      = (const float*)d_in[1];
    const float* theta_w = (const float*)d_in[2];
    const float* phi_w   = (const float*)d_in[3];
    const float* w_w     = (const float*)d_in[4];
    float* out           = (float*)d_out;

    dim3 gp(NP / TQ, BATCH);
    proj_kernel<<<gp, PT>>>(x, theta_w, phi_w, gw);

    dim3 ga(NP / TQ, SPLITS, BATCH);
    attn_kernel<<<ga, TQ>>>();

    merge_out_kernel<<<gp, MT>>>(x, w_w, out);
}